// round 10
// baseline (speedup 1.0000x reference)
#include <cuda_runtime.h>
#include <cstdint>

// Depthwise separable 4x4 blur, filter [1,3,3,1] (x) [1,3,3,1] / 64.
// Input  (8, 256, 64, 512) fp32, W-pad circular(1), H-pad reflect(1).
// Output (8, 256, 63, 511) fp32.
//
// R10: per-warp-autonomous cp.async (LDGSTS.cg) pipeline. Each warp owns a
// 128-col strip (+halo, circular wrap) of one image, staged through its own
// private 8-stage smem ring. Completion via per-thread cp.async.wait_group —
// zero inter-warp synchronization (no __syncthreads, no mbarriers; cannot
// deadlock). 7 rows x 576B in flight per warp, independent of registers ->
// low regs, high occupancy, ~1.8x the in-flight read bytes of the register
// ring. Consume = 2 conflict-free LDS.128 -> R3's hblur/vblur/store path.

#define W       512
#define H       64
#define OW      511
#define OH      63
#define STAGES  8
#define STAGE_F 144      // floats per stage: strip cols (128w-8 .. 128w+135)
#define PRE     7        // rows in flight

// ── PTX helpers ──────────────────────────────────────────────────────────
__device__ __forceinline__ void cp_async16(uint32_t dst, const float* src) {
    asm volatile("cp.async.cg.shared.global [%0], [%1], 16;"
                 :: "r"(dst), "l"(src) : "memory");
}
__device__ __forceinline__ void cp_commit() {
    asm volatile("cp.async.commit_group;" ::: "memory");
}
template <int N>
__device__ __forceinline__ void cp_wait() {
    asm volatile("cp.async.wait_group %0;" :: "n"(N) : "memory");
}
__device__ __forceinline__ void lds128(float4& v, uint32_t a) {
    asm volatile("ld.shared.v4.f32 {%0,%1,%2,%3}, [%4];"
                 : "=f"(v.x), "=f"(v.y), "=f"(v.z), "=f"(v.w)
                 : "r"(a) : "memory");
}

// ── math (identical to R3) ───────────────────────────────────────────────
__device__ __forceinline__ float4 f4_hblur(const float4& A, const float4& B)
{
    // outputs ox = 4t+1..4t+4 from src cols A=[4t..4t+3], B=[4t+4..4t+7]
    float4 r;
    r.x = (A.x + A.w) + 3.0f * (A.y + A.z);
    r.y = (A.y + B.x) + 3.0f * (A.z + A.w);
    r.z = (A.z + B.y) + 3.0f * (A.w + B.x);
    r.w = (A.w + B.z) + 3.0f * (B.x + B.y);
    return r;
}
__device__ __forceinline__ float4 f4_vblur(const float4& a, const float4& b,
                                           const float4& c, const float4& d)
{
    float4 r;
    r.x = ((a.x + d.x) + 3.0f * (b.x + c.x)) * (1.0f / 64.0f);
    r.y = ((a.y + d.y) + 3.0f * (b.y + c.y)) * (1.0f / 64.0f);
    r.z = ((a.z + d.z) + 3.0f * (b.z + c.z)) * (1.0f / 64.0f);
    r.w = ((a.w + d.w) + 3.0f * (b.w + c.w)) * (1.0f / 64.0f);
    return r;
}

__global__ __launch_bounds__(128) void Blur_49976239456711_kernel(
    const float* __restrict__ in, float* __restrict__ out)
{
    // Per-warp private stage rings: 4 warps x 8 stages x 144 floats = 18 KB.
    __shared__ __align__(16) float buf[4][STAGES][STAGE_F];

    const int t    = threadIdx.x;          // 0..127; owns output cols 4t+1..4t+4
    const int lane = t & 31;
    const int wid  = t >> 5;
    const int img  = blockIdx.x;           // 0..2047

    const float* __restrict__ src = in  + (size_t)img * (H * W);
    float*       __restrict__ dst = out + (size_t)img * (OH * OW);

    const uint32_t ring_b =
        (uint32_t)__cvta_generic_to_shared(&buf[wid][0][0]);

    // Warp strip: src cols base_col .. base_col+143 (circular), base 16B-aligned.
    const int base_col = 128 * wid - 8;

    // Produce src row y into stage (y & 7): 36 quads, circular col wrap.
    auto issue_row = [&](int y) {
        const float* rowp = src + y * W;
        const uint32_t db = ring_b + (uint32_t)(y & (STAGES - 1)) * (STAGE_F * 4);
        {
            const int col = (base_col + 4 * lane) & (W - 1);
            cp_async16(db + 16 * lane, rowp + col);
        }
        if (lane < 4) {
            const int q   = 32 + lane;
            const int col = (base_col + 4 * q) & (W - 1);
            cp_async16(db + 16 * q, rowp + col);
        }
        cp_commit();
    };

    // Consume src row y: horizontal blur from two aligned LDS.128.
    // rel offset of src col (128w + 4l) is 4l+8.
    auto consume = [&](int y) -> float4 {
        const uint32_t b = ring_b + (uint32_t)(y & (STAGES - 1)) * (STAGE_F * 4)
                                  + (uint32_t)(16 * lane);
        float4 A, B;
        lds128(A, b + 32);    // rel floats 4l+8  .. 4l+11 = src cols 4t..4t+3
        lds128(B, b + 48);    // rel floats 4l+12 .. 4l+15 = src cols 4t+4..4t+7
        return f4_hblur(A, B);
    };

    const int  ox0  = 4 * t + 1;
    const bool fullq = (t < 127);           // t=127 covers ox 509,510,(skip),0
    auto store4 = [&](int oy, const float4& v) {
        float* row = dst + oy * OW;
        row[ox0]     = v.x;
        row[ox0 + 1] = v.y;
        if (fullq) {
            row[ox0 + 2] = v.z;
            row[ox0 + 3] = v.w;
        } else {
            row[0] = v.w;                   // circular wrap: ox=0
        }
    };

    // ── prologue: rows 0..6 in flight ──
    #pragma unroll
    for (int y = 0; y < PRE; ++y) issue_row(y);

    // Initial vertical window (reflect: padded 0 -> src 1, padded 1 -> src 0,
    // padded 2 -> src 1). Rows consumed strictly in order 0,1,2,...
    issue_row(PRE);      cp_wait<PRE>();
    float4 w1 = consume(0);                 // HB[padded 1] = src row 0
    issue_row(PRE + 1);  cp_wait<PRE>();
    float4 w0 = consume(1);                 // HB[padded 0] = src row 1
    float4 w2 = w0;                         // HB[padded 2] = src row 1

    // Main loop: consume src row y, emit output oy = y-2.
    for (int y = 2; y < H; ++y) {
        if (y + PRE < H) {                  // y <= 56: keep 7 rows in flight
            issue_row(y + PRE);
            cp_wait<PRE>();                 // rows <= y complete
        } else {
            cp_wait<0>();                   // tail drain (no-op after first)
        }
        const float4 h = consume(y);
        store4(y - 2, f4_vblur(w0, w1, w2, h));
        w0 = w1; w1 = w2; w2 = h;
    }

    // oy = 62: padded rows 62..65 -> src 61,62,63,62 = (w0, w1, w2, w1).
    {
        float4 o;
        o.x = ((w0.x + w1.x) + 3.0f * (w1.x + w2.x)) * (1.0f / 64.0f);
        o.y = ((w0.y + w1.y) + 3.0f * (w1.y + w2.y)) * (1.0f / 64.0f);
        o.z = ((w0.z + w1.z) + 3.0f * (w1.z + w2.z)) * (1.0f / 64.0f);
        o.w = ((w0.w + w1.w) + 3.0f * (w1.w + w2.w)) * (1.0f / 64.0f);
        store4(OH - 1, o);
    }
}

extern "C" void kernel_launch(void* const* d_in, const int* in_sizes, int n_in,
                              void* d_out, int out_size)
{
    const float* h = (const float*)d_in[0];
    float* out = (float*)d_out;

    const int n_img = 8 * 256;              // 2048 images of 64x512
    Blur_49976239456711_kernel<<<n_img, 128>>>(h, out);
}

// round 11
// speedup vs baseline: 1.3043x; 1.3043x over previous
#include <cuda_runtime.h>

// Depthwise separable 4x4 blur, filter [1,3,3,1] (x) [1,3,3,1] / 64.
// Input  (8, 256, 64, 512) fp32, W-pad circular(1), H-pad reflect(1).
// Output (8, 256, 63, 511) fp32.
//
// R11 = R3 (register prefetch ring) with:
//  - ring depth 4 -> 8 (16 LDG.128 in flight per thread, ~160KB/SM reads)
//  - __ldcs / __stcs streaming hints (single-use data, evict-first)
//  - main loop = exactly 56 trips @ unroll 8 (static ring indices), last 6
//    rows peeled with compile-time constants (R4 lesson: dynamic ring index
//    => local-memory spill).

#define W      512
#define H      64
#define OW     511
#define OH     63
#define DEPTH  8

__device__ __forceinline__ float4 f4_vblur(const float4& a, const float4& b,
                                           const float4& c, const float4& d)
{
    float4 r;
    r.x = ((a.x + d.x) + 3.0f * (b.x + c.x)) * (1.0f / 64.0f);
    r.y = ((a.y + d.y) + 3.0f * (b.y + c.y)) * (1.0f / 64.0f);
    r.z = ((a.z + d.z) + 3.0f * (b.z + c.z)) * (1.0f / 64.0f);
    r.w = ((a.w + d.w) + 3.0f * (b.w + c.w)) * (1.0f / 64.0f);
    return r;
}

__device__ __forceinline__ float4 f4_hblur(const float4& A, const float4& B)
{
    // outputs ox = 4t+1..4t+4 from src cols A=[4t..4t+3], B=[4t+4..4t+7]
    float4 r;
    r.x = (A.x + A.w) + 3.0f * (A.y + A.z);
    r.y = (A.y + B.x) + 3.0f * (A.z + A.w);
    r.z = (A.z + B.y) + 3.0f * (A.w + B.x);
    r.w = (A.w + B.z) + 3.0f * (B.x + B.y);
    return r;
}

__global__ __launch_bounds__(128) void Blur_49976239456711_kernel(
    const float* __restrict__ in, float* __restrict__ out)
{
    const int t   = threadIdx.x;           // 0..127, owns src cols 4t..4t+3
    const int img = blockIdx.x;            // 0..2047

    const float* __restrict__ src = in  + (size_t)img * (H * W);
    float*       __restrict__ dst = out + (size_t)img * (OH * OW);

    const int cA = 4 * t;
    const int cB = (4 * t + 4) & (W - 1);  // wraps 512 -> 0 for t=127

    const int  ox0  = 4 * t + 1;
    const bool full = (t < 127);            // t=127 covers ox 509,510,(skip),0

    auto store4 = [&](int oy, const float4& v) {
        float* row = dst + oy * OW;
        __stcs(row + ox0,     v.x);
        __stcs(row + ox0 + 1, v.y);
        if (full) {
            __stcs(row + ox0 + 2, v.z);
            __stcs(row + ox0 + 3, v.w);
        } else {
            __stcs(row + 0, v.w);           // circular wrap: ox=0
        }
    };

    // ── 8-deep prefetch ring: slot s holds a src row, loaded 8 iters ahead ──
    float4 pa[DEPTH], pb[DEPTH];

    auto issue = [&](int y, int s) {
        pa[s] = __ldcs(reinterpret_cast<const float4*>(src + y * W + cA));
        pb[s] = __ldcs(reinterpret_cast<const float4*>(src + y * W + cB));
    };

    // Prologue: prefetch rows 2..9 into slots 0..7 (consumed at oy = 0..7).
    #pragma unroll
    for (int s = 0; s < DEPTH; ++s) issue(s + 2, s);

    // Initial vertical window (reflect: padded 0 -> src 1, padded 1 -> src 0,
    // padded 2 -> src 1). Direct loads for src rows 1 and 0.
    const float4 A1 = __ldcs(reinterpret_cast<const float4*>(src + 1 * W + cA));
    const float4 B1 = __ldcs(reinterpret_cast<const float4*>(src + 1 * W + cB));
    const float4 A0 = __ldcs(reinterpret_cast<const float4*>(src + 0 * W + cA));
    const float4 B0 = __ldcs(reinterpret_cast<const float4*>(src + 0 * W + cB));

    float4 hb0 = f4_hblur(A1, B1);   // HB[padded 0] = src row 1
    float4 hb1 = f4_hblur(A0, B0);   // HB[padded 1] = src row 0
    float4 hb2 = hb0;                // HB[padded 2] = src row 1
    float4 hb3;

    // Main loop: 56 trips, unroll 8 -> ring index oy&7 is static in every
    // unrolled body position. Output oy consumes src row oy+2 from slot
    // (oy&7), then refills that slot with src row oy+10 (rows 10..63).
    #pragma unroll 8
    for (int oy = 0; oy < 56; ++oy) {
        const int s = oy & (DEPTH - 1);
        hb3 = f4_hblur(pa[s], pb[s]);              // src row oy+2
        const int ny = oy + 10;
        if (ny < H) issue(ny, s);                  // oy <= 53
        store4(oy, f4_vblur(hb0, hb1, hb2, hb3));
        hb0 = hb1; hb1 = hb2; hb2 = hb3;
    }

    // Peeled tail oy = 56..61: constant trip count, fully unrolled ->
    // slot indices are compile-time constants. No refills (rows exhausted).
    #pragma unroll
    for (int oy = 56; oy < 62; ++oy) {
        const int s = oy & (DEPTH - 1);
        hb3 = f4_hblur(pa[s], pb[s]);              // src row oy+2
        store4(oy, f4_vblur(hb0, hb1, hb2, hb3));
        hb0 = hb1; hb1 = hb2; hb2 = hb3;
    }

    // oy = 62: padded rows 62..65 -> src 61,62,63,62; the last window is
    // (hb0, hb1, hb2, hb1-equivalent): padded 65 reflects to src row 62,
    // whose hblur is hb1 (src 62 = row consumed at oy=60).
    {
        float4 o;
        o.x = ((hb0.x + hb1.x) + 3.0f * (hb1.x + hb2.x)) * (1.0f / 64.0f);
        o.y = ((hb0.y + hb1.y) + 3.0f * (hb1.y + hb2.y)) * (1.0f / 64.0f);
        o.z = ((hb0.z + hb1.z) + 3.0f * (hb1.z + hb2.z)) * (1.0f / 64.0f);
        o.w = ((hb0.w + hb1.w) + 3.0f * (hb1.w + hb2.w)) * (1.0f / 64.0f);
        store4(OH - 1, o);
    }
}

extern "C" void kernel_launch(void* const* d_in, const int* in_sizes, int n_in,
                              void* d_out, int out_size)
{
    const float* h = (const float*)d_in[0];
    float* out = (float*)d_out;

    const int n_img = 8 * 256;              // 2048 images of 64x512
    Blur_49976239456711_kernel<<<n_img, 128>>>(h, out);
}